// round 14
// baseline (speedup 1.0000x reference)
#include <cuda_runtime.h>

// out[b,i,j] = W[b,i,j] - (dot(W[b,i,:], x[b,:]) + ETA*gL[b,i]) * x[b,j]
// B=64, D=1024, fp32. Purely HBM-bound: 256MB read + 256MB write.
//
// R14: software-pipelined multi-tile. Each warp owns 4 rows of one batch;
// the LDG front-batch for row t+1 is issued BEFORE the store burst of row t,
// so every warp keeps read and write streams simultaneously outstanding
// (eliminates CTA-boundary read bubbles; grid 8192 -> 2048). x staged in
// smem once per block, amortized over 32 rows. Structure per row identical
// to the proven R6/R13 kernel (register-resident W row, shuffle reduce).

#define B_DIM 64
#define D_DIM 1024
#define ETA 0.01f
#define WARPS 8
#define TILES 4                     // rows per warp
#define ROWS_PER_BLOCK (WARPS * TILES)   // 32
#define THREADS 256
#define F4 8                        // 1024 floats / 32 lanes / 4 per float4

__global__ __launch_bounds__(THREADS, 2)
void ttt_update_kernel(const float* __restrict__ W,
                       const float* __restrict__ x,
                       const float* __restrict__ gL,
                       float* __restrict__ out)
{
    __shared__ float4 xs[D_DIM / 4];   // 4 KB: x[b], reused by 32 rows

    const int groups_per_batch = D_DIM / ROWS_PER_BLOCK;   // 32
    const int b  = blockIdx.x / groups_per_batch;
    const int rg = blockIdx.x % groups_per_batch;

    xs[threadIdx.x] =
        reinterpret_cast<const float4*>(x + (size_t)b * D_DIM)[threadIdx.x];

    const int warp = threadIdx.x >> 5;
    const int lane = threadIdx.x & 31;
    // Warp's rows: base + warp + t*8  (t = 0..3)
    const int row0 = rg * ROWS_PER_BLOCK + warp;

    const size_t base = ((size_t)b * D_DIM + row0) * D_DIM;
    const float4* __restrict__ wrow = reinterpret_cast<const float4*>(W + base);
    float4* __restrict__       orow = reinterpret_cast<float4*>(out + base);
    const float* __restrict__  grow = gL + (size_t)b * D_DIM + row0;
    const size_t row_stride4 = (size_t)WARPS * D_DIM / 4;   // 8 rows in float4s

    // Prologue: front-batch row 0's 8 LDG.128s
    float4 wv[F4];
#pragma unroll
    for (int k = 0; k < F4; k++)
        wv[k] = wrow[lane + k * 32];
    float g = grow[0];

    __syncthreads();   // xs ready (hidden under prologue LDG latency)

    float4 xv[F4];
#pragma unroll
    for (int k = 0; k < F4; k++)
        xv[k] = xs[lane + k * 32];

#pragma unroll
    for (int t = 0; t < TILES; t++) {
        // Issue next row's read burst BEFORE this row's compute+store, so
        // reads stay in flight while stores drain.
        float4 nv[F4];
        if (t + 1 < TILES) {
            const float4* __restrict__ nrow = wrow + (t + 1) * row_stride4;
#pragma unroll
            for (int k = 0; k < F4; k++)
                nv[k] = nrow[lane + k * 32];
        }
        const float gnext = (t + 1 < TILES) ? grow[(t + 1) * WARPS] : 0.0f;

        // Dot product on current row
        float acc = 0.0f;
#pragma unroll
        for (int k = 0; k < F4; k++) {
            acc += wv[k].x * xv[k].x;
            acc += wv[k].y * xv[k].y;
            acc += wv[k].z * xv[k].z;
            acc += wv[k].w * xv[k].w;
        }
#pragma unroll
        for (int off = 16; off > 0; off >>= 1)
            acc += __shfl_xor_sync(0xffffffffu, acc, off);

        const float coeff = acc + ETA * g;

        // Store burst for current row
        float4* __restrict__ od = orow + t * row_stride4;
#pragma unroll
        for (int k = 0; k < F4; k++) {
            float4 o;
            o.x = wv[k].x - coeff * xv[k].x;
            o.y = wv[k].y - coeff * xv[k].y;
            o.z = wv[k].z - coeff * xv[k].z;
            o.w = wv[k].w - coeff * xv[k].w;
            od[lane + k * 32] = o;
        }

        // Rotate pipeline
        if (t + 1 < TILES) {
#pragma unroll
            for (int k = 0; k < F4; k++)
                wv[k] = nv[k];
            g = gnext;
        }
    }
}

extern "C" void kernel_launch(void* const* d_in, const int* in_sizes, int n_in,
                              void* d_out, int out_size)
{
    const float* W  = (const float*)d_in[0];   // [B, D, D]
    const float* x  = (const float*)d_in[1];   // [B, D, 1]
    const float* gL = (const float*)d_in[2];   // [B, D, 1]
    float* out = (float*)d_out;                // [B, D, D]

    const int grid = B_DIM * (D_DIM / ROWS_PER_BLOCK);   // 64 * 32 = 2048
    ttt_update_kernel<<<grid, THREADS>>>(W, x, gL, out);
}